// round 3
// baseline (speedup 1.0000x reference)
#include <cuda_runtime.h>
#include <cuda_bf16.h>
#include <cstdint>

#define D 128
#define NMAX 50048
#define EMAX 800000
#define RPB 8   // rows per gemm block

// Scratch (static device arrays; no allocation anywhere)
__device__ float g_h[(size_t)NMAX * D];     // per-layer transformed features
__device__ float g_agg[(size_t)NMAX * D];   // layer-1 aggregation buffer
__device__ float g_dinv[NMAX];              // deg count, then rsqrt(deg+1)
__device__ int   g_src[EMAX];
__device__ int   g_dst[EMAX];
__device__ float g_norm[EMAX];
__device__ int   g_is64;

// ---------------------------------------------------------------------------
// dtype detection: int64 edge_index has zero high words at odd int32 offsets
// ---------------------------------------------------------------------------
__global__ void k_detect(const int* __restrict__ ei32) {
    if (threadIdx.x == 0) {
        int all_zero = 1;
        #pragma unroll
        for (int i = 1; i < 32; i += 2)
            if (ei32[i] != 0) all_zero = 0;
        g_is64 = all_zero;
    }
}

// decode edges into int32 src/dst, clamped to [0, n)
__global__ void k_decode(const void* __restrict__ ei, int E, int n) {
    int i = blockIdx.x * blockDim.x + threadIdx.x;
    if (i >= E) return;
    int s, d;
    if (g_is64) {
        const long long* p = (const long long*)ei;
        s = (int)p[i];
        d = (int)p[(size_t)E + i];
    } else {
        const int* p = (const int*)ei;
        s = p[i];
        d = p[E + i];
    }
    s = min(max(s, 0), n - 1);
    d = min(max(d, 0), n - 1);
    g_src[i] = s;
    g_dst[i] = d;
}

// ---------------------------------------------------------------------------
// degree pipeline
// ---------------------------------------------------------------------------
__global__ void k_zero_dinv(int n) {
    int i = blockIdx.x * blockDim.x + threadIdx.x;
    if (i < n) g_dinv[i] = 0.0f;
}

__global__ void k_count(int E) {
    int i = blockIdx.x * blockDim.x + threadIdx.x;
    if (i < E) atomicAdd(&g_dinv[g_dst[i]], 1.0f);   // result unused -> RED
}

__global__ void k_dinv(int n) {
    int i = blockIdx.x * blockDim.x + threadIdx.x;
    if (i < n) g_dinv[i] = rsqrtf(g_dinv[i] + 1.0f);
}

__global__ void k_norm(int E) {
    int i = blockIdx.x * blockDim.x + threadIdx.x;
    if (i < E) g_norm[i] = g_dinv[g_src[i]] * g_dinv[g_dst[i]];
}

// ---------------------------------------------------------------------------
// GEMM: g_h[row][j] = sum_k in'[row][k] * W[k][j]
//   in' = relu(in + bias_in) if relu_in, else in     (in = x_or_null ?: g_agg)
//   agg[row][j] initialized to h*dinv^2 (+ b_out)    (agg = agg_or_null ?: g_agg)
// blockDim = 128 (one thread per output column), RPB rows per block.
// ---------------------------------------------------------------------------
__global__ void k_gemm(const float* __restrict__ x_or_null,
                       const float* __restrict__ W,
                       const float* __restrict__ bias_in, int relu_in,
                       float* __restrict__ agg_or_null,
                       const float* __restrict__ b_out,
                       int n)
{
    const float* in  = x_or_null   ? x_or_null   : g_agg;
    float*       agg = agg_or_null ? agg_or_null : g_agg;

    __shared__ float s[D][RPB];   // transposed: s[k][r]
    const int t = threadIdx.x;
    const int row0 = blockIdx.x * RPB;

    const float bin = relu_in ? bias_in[t] : 0.0f;

#pragma unroll
    for (int r = 0; r < RPB; r++) {
        int row = row0 + r;
        float v = 0.0f;
        if (row < n) {
            v = in[(size_t)row * D + t];
            if (relu_in) v = fmaxf(v + bin, 0.0f);
        }
        s[t][r] = v;
    }
    __syncthreads();

    float acc[RPB];
#pragma unroll
    for (int r = 0; r < RPB; r++) acc[r] = 0.0f;

#pragma unroll 4
    for (int k = 0; k < D; k++) {
        float w = W[k * D + t];                 // coalesced across threads
        float4 a0 = *(const float4*)&s[k][0];   // broadcast LDS.128
        float4 a1 = *(const float4*)&s[k][4];
        acc[0] = fmaf(a0.x, w, acc[0]);
        acc[1] = fmaf(a0.y, w, acc[1]);
        acc[2] = fmaf(a0.z, w, acc[2]);
        acc[3] = fmaf(a0.w, w, acc[3]);
        acc[4] = fmaf(a1.x, w, acc[4]);
        acc[5] = fmaf(a1.y, w, acc[5]);
        acc[6] = fmaf(a1.z, w, acc[6]);
        acc[7] = fmaf(a1.w, w, acc[7]);
    }

    const float bo = b_out ? b_out[t] : 0.0f;
#pragma unroll
    for (int r = 0; r < RPB; r++) {
        int row = row0 + r;
        if (row >= n) break;
        float h = acc[r];
        g_h[(size_t)row * D + t] = h;
        float di = g_dinv[row];
        agg[(size_t)row * D + t] = fmaf(h, di * di, bo);
    }
}

// ---------------------------------------------------------------------------
// Scatter: one warp per edge; each lane handles one float4 of the 512B row.
// agg[dst] += g_h[src] * g_norm[e]   via red.global.add.v4.f32
// ---------------------------------------------------------------------------
__global__ void k_scatter(float* __restrict__ agg_or_null, int E)
{
    float* agg = agg_or_null ? agg_or_null : g_agg;

    int gt = blockIdx.x * blockDim.x + threadIdx.x;
    int e = gt >> 5;
    int lane = gt & 31;
    if (e >= E) return;

    int src    = g_src[e];       // broadcast within warp (same address)
    int dst    = g_dst[e];
    float norm = g_norm[e];

    const float4 v = *(const float4*)&g_h[(size_t)src * D + lane * 4];
    float* p = &agg[(size_t)dst * D + lane * 4];
    asm volatile("red.global.add.v4.f32 [%0], {%1,%2,%3,%4};"
                 :: "l"(p), "f"(v.x * norm), "f"(v.y * norm),
                    "f"(v.z * norm), "f"(v.w * norm)
                 : "memory");
}

// ---------------------------------------------------------------------------
// launch
// ---------------------------------------------------------------------------
extern "C" void kernel_launch(void* const* d_in, const int* in_sizes, int n_in,
                              void* d_out, int out_size)
{
    const float* x   = (const float*)d_in[0];
    const void*  ei  = d_in[1];
    const float* W1  = (const float*)d_in[2];
    const float* b1  = (const float*)d_in[3];
    const float* W2  = (const float*)d_in[4];
    const float* b2  = (const float*)d_in[5];
    float*       out = (float*)d_out;

    const int N = in_sizes[0] / D;
    const int E = in_sizes[1] / 2;

    const int TPB = 256;
    const int eb  = (E + TPB - 1) / TPB;
    const int nb  = (N + TPB - 1) / TPB;

    // edge decode + degrees -> dinv -> per-edge norm
    k_detect<<<1, 32>>>((const int*)ei);
    k_decode<<<eb, TPB>>>(ei, E, N);
    k_zero_dinv<<<nb, TPB>>>(N);
    k_count<<<eb, TPB>>>(E);
    k_dinv<<<nb, TPB>>>(N);
    k_norm<<<eb, TPB>>>(E);

    const int gemm_blocks = (N + RPB - 1) / RPB;
    const long long scatter_threads = (long long)E * 32;
    const int scatter_blocks = (int)((scatter_threads + TPB - 1) / TPB);

    // layer 1: h1 = x @ W1 ; agg1 = h1*dinv^2 ; agg1 += scatter
    k_gemm<<<gemm_blocks, D>>>(x, W1, nullptr, 0, nullptr, nullptr, N);
    k_scatter<<<scatter_blocks, TPB>>>(nullptr, E);

    // layer 2: in' = relu(agg1 + b1) ; h2 = in' @ W2 ; out = h2*dinv^2 + b2 ; out += scatter
    k_gemm<<<gemm_blocks, D>>>(nullptr, W2, b1, 1, out, b2, N);
    k_scatter<<<scatter_blocks, TPB>>>(out, E);
}

// round 4
// speedup vs baseline: 1.1291x; 1.1291x over previous
#include <cuda_runtime.h>
#include <cuda_bf16.h>
#include <cstdint>

#define D 128
#define NMAX 50048
#define EMAX 800000
#define RPB 8   // rows per gemm block

// Scratch (static device arrays; no allocation anywhere)
__device__ float g_h[(size_t)NMAX * D];     // per-layer transformed features
__device__ float g_agg[(size_t)NMAX * D];   // layer-1 aggregated output
__device__ float g_dinv[NMAX];              // rsqrt(deg+1)
__device__ int   g_deg[NMAX];
__device__ int   g_off[NMAX + 1];           // CSR row offsets (by dst)
__device__ int   g_cur[NMAX];               // fill cursors
__device__ int   g_src[EMAX];
__device__ int   g_dst[EMAX];
__device__ int2  g_ce[EMAX];                // CSR entries: (src, bits(dinv[src]))
__device__ int   g_is64;

// ---------------------------------------------------------------------------
// dtype detection: int64 edge_index has zero high words at odd int32 offsets
// ---------------------------------------------------------------------------
__global__ void k_detect(const int* __restrict__ ei32) {
    if (threadIdx.x == 0) {
        int all_zero = 1;
        #pragma unroll
        for (int i = 1; i < 32; i += 2)
            if (ei32[i] != 0) all_zero = 0;
        g_is64 = all_zero;
    }
}

__global__ void k_zero_deg(int n) {
    int i = blockIdx.x * blockDim.x + threadIdx.x;
    if (i < n) g_deg[i] = 0;
}

// decode edges (int64 or int32) into clamped int32 src/dst + degree count
__global__ void k_decode(const void* __restrict__ ei, int E, int n) {
    int i = blockIdx.x * blockDim.x + threadIdx.x;
    if (i >= E) return;
    int s, d;
    if (g_is64) {
        const long long* p = (const long long*)ei;
        s = (int)p[i];
        d = (int)p[(size_t)E + i];
    } else {
        const int* p = (const int*)ei;
        s = p[i];
        d = p[E + i];
    }
    s = min(max(s, 0), n - 1);
    d = min(max(d, 0), n - 1);
    g_src[i] = s;
    g_dst[i] = d;
    atomicAdd(&g_deg[d], 1);
}

__global__ void k_dinv(int n) {
    int i = blockIdx.x * blockDim.x + threadIdx.x;
    if (i < n) g_dinv[i] = rsqrtf((float)g_deg[i] + 1.0f);
}

// ---------------------------------------------------------------------------
// single-block exclusive scan of g_deg -> g_off (and g_cur copy), n <= ~64k
// ---------------------------------------------------------------------------
__global__ void k_scan(int n) {
    __shared__ int warp_sums[32];
    const int t = threadIdx.x;                 // 1024 threads
    const int chunk = (n + 1023) >> 10;
    const int begin = t * chunk;
    const int end   = min(begin + chunk, n);

    int s = 0;
    for (int i = begin; i < end; i++) s += g_deg[i];

    // block exclusive scan of per-thread sums
    const int lane = t & 31, w = t >> 5;
    int v = s;
    #pragma unroll
    for (int o = 1; o < 32; o <<= 1) {
        int x = __shfl_up_sync(0xFFFFFFFFu, v, o);
        if (lane >= o) v += x;
    }
    if (lane == 31) warp_sums[w] = v;
    __syncthreads();
    if (w == 0) {
        int ws = warp_sums[lane];
        #pragma unroll
        for (int o = 1; o < 32; o <<= 1) {
            int x = __shfl_up_sync(0xFFFFFFFFu, ws, o);
            if (lane >= o) ws += x;
        }
        warp_sums[lane] = ws;
    }
    __syncthreads();
    int run = (v - s) + (w > 0 ? warp_sums[w - 1] : 0);

    for (int i = begin; i < end; i++) {
        g_off[i] = run;
        g_cur[i] = run;
        run += g_deg[i];
    }
    if (end == n && begin < n) g_off[n] = run;
}

// fill CSR: entry = (src, dinv[src])
__global__ void k_fill(int E) {
    int i = blockIdx.x * blockDim.x + threadIdx.x;
    if (i >= E) return;
    int s = g_src[i];
    int pos = atomicAdd(&g_cur[g_dst[i]], 1);
    g_ce[pos] = make_int2(s, __float_as_int(g_dinv[s]));
}

// ---------------------------------------------------------------------------
// GEMM: g_h[row][j] = sum_k in'[row][k] * W[k][j]
//   in' = relu(in) if relu_in (bias already folded in by k_agg), else in
//   in  = x_or_null ? x_or_null : g_agg
// blockDim = 128 (one thread per output column), RPB rows per block.
// ---------------------------------------------------------------------------
__global__ void k_gemm(const float* __restrict__ x_or_null,
                       const float* __restrict__ W,
                       int relu_in, int n)
{
    const float* in = x_or_null ? x_or_null : g_agg;

    __shared__ float s[D][RPB];   // transposed: s[k][r]
    const int t = threadIdx.x;
    const int row0 = blockIdx.x * RPB;

#pragma unroll
    for (int r = 0; r < RPB; r++) {
        int row = row0 + r;
        float v = 0.0f;
        if (row < n) {
            v = in[(size_t)row * D + t];
            if (relu_in) v = fmaxf(v, 0.0f);
        }
        s[t][r] = v;
    }
    __syncthreads();

    float acc[RPB];
#pragma unroll
    for (int r = 0; r < RPB; r++) acc[r] = 0.0f;

#pragma unroll 4
    for (int k = 0; k < D; k++) {
        float w = W[k * D + t];                 // coalesced across threads
        float4 a0 = *(const float4*)&s[k][0];   // broadcast LDS.128
        float4 a1 = *(const float4*)&s[k][4];
        acc[0] = fmaf(a0.x, w, acc[0]);
        acc[1] = fmaf(a0.y, w, acc[1]);
        acc[2] = fmaf(a0.z, w, acc[2]);
        acc[3] = fmaf(a0.w, w, acc[3]);
        acc[4] = fmaf(a1.x, w, acc[4]);
        acc[5] = fmaf(a1.y, w, acc[5]);
        acc[6] = fmaf(a1.z, w, acc[6]);
        acc[7] = fmaf(a1.w, w, acc[7]);
    }

#pragma unroll
    for (int r = 0; r < RPB; r++) {
        int row = row0 + r;
        if (row >= n) break;
        g_h[(size_t)row * D + t] = acc[r];
    }
}

// ---------------------------------------------------------------------------
// Gather-aggregate: one warp per dst row, lane owns one float4 of 128 cols.
// out[d] = dinv[d] * sum_{e in CSR[d]} dinv[src]*h[src]  +  dinv[d]^2*h[d] + b
// ---------------------------------------------------------------------------
__global__ void k_agg(float* __restrict__ out_or_null,
                      const float* __restrict__ b, int n)
{
    float* out = out_or_null ? out_or_null : g_agg;

    const int warp = (blockIdx.x * blockDim.x + threadIdx.x) >> 5;
    const int lane = threadIdx.x & 31;
    if (warp >= n) return;

    const int d   = warp;
    const int beg = g_off[d];
    const int end = g_off[d + 1];

    float4 acc = make_float4(0.f, 0.f, 0.f, 0.f);
    for (int j = beg; j < end; j++) {
        int2 e = g_ce[j];                      // broadcast 8B load
        float w = __int_as_float(e.y);
        const float4 v = *(const float4*)&g_h[(size_t)e.x * D + lane * 4];
        acc.x = fmaf(w, v.x, acc.x);
        acc.y = fmaf(w, v.y, acc.y);
        acc.z = fmaf(w, v.z, acc.z);
        acc.w = fmaf(w, v.w, acc.w);
    }

    const float di  = g_dinv[d];
    const float di2 = di * di;
    const float4 hv = *(const float4*)&g_h[(size_t)d * D + lane * 4];
    const float4 bv = *(const float4*)&b[lane * 4];

    float4 o;
    o.x = fmaf(di, acc.x, fmaf(di2, hv.x, bv.x));
    o.y = fmaf(di, acc.y, fmaf(di2, hv.y, bv.y));
    o.z = fmaf(di, acc.z, fmaf(di2, hv.z, bv.z));
    o.w = fmaf(di, acc.w, fmaf(di2, hv.w, bv.w));
    *(float4*)&out[(size_t)d * D + lane * 4] = o;
}

// ---------------------------------------------------------------------------
// launch
// ---------------------------------------------------------------------------
extern "C" void kernel_launch(void* const* d_in, const int* in_sizes, int n_in,
                              void* d_out, int out_size)
{
    const float* x   = (const float*)d_in[0];
    const void*  ei  = d_in[1];
    const float* W1  = (const float*)d_in[2];
    const float* b1  = (const float*)d_in[3];
    const float* W2  = (const float*)d_in[4];
    const float* b2  = (const float*)d_in[5];
    float*       out = (float*)d_out;

    const int N = in_sizes[0] / D;
    const int E = in_sizes[1] / 2;

    const int TPB = 256;
    const int eb  = (E + TPB - 1) / TPB;
    const int nb  = (N + TPB - 1) / TPB;

    // preprocessing: decode -> deg -> dinv -> CSR(off, entries)
    k_detect<<<1, 32>>>((const int*)ei);
    k_zero_deg<<<nb, TPB>>>(N);
    k_decode<<<eb, TPB>>>(ei, E, N);
    k_dinv<<<nb, TPB>>>(N);
    k_scan<<<1, 1024>>>(N);
    k_fill<<<eb, TPB>>>(E);

    const int gemm_blocks = (N + RPB - 1) / RPB;
    const int agg_blocks  = (N * 32 + TPB - 1) / TPB;   // one warp per row

    // layer 1: h1 = x @ W1 ; agg1 = gather(h1) + b1
    k_gemm<<<gemm_blocks, D>>>(x, W1, 0, N);
    k_agg<<<agg_blocks, TPB>>>(nullptr, b1, N);

    // layer 2: h2 = relu(agg1) @ W2 ; out = gather(h2) + b2
    k_gemm<<<gemm_blocks, D>>>(nullptr, W2, 1, N);
    k_agg<<<agg_blocks, TPB>>>(out, b2, N);
}